// round 1
// baseline (speedup 1.0000x reference)
#include <cuda_runtime.h>
#include <cuda_bf16.h>

// ContourIntegrationLayer: depthwise 3x3 conv (center tap zeroed) + residual.
// x: [B,H,W,C]=[32,56,56,256] f32, kernel: [3,3,C] f32, out: same as x.
//
// Strategy: row-register sliding window. Thread = (b, h-group of RH rows, c4).
// Sweep w left->right; each step loads RH+2 fresh float4 rows at column wl and
// FMAs them into 3 rotating accumulators (output cols wl-1, wl, wl+1).
// W reuse is perfect; H read amplification = (RH+2)/RH = 1.67x -> L2 traffic
// stays below the DRAM floor, so the kernel is DRAM-streaming-bound.

#define BB 32
#define HH 56
#define WW 56
#define CC 256
#define C4 (CC / 4)      // 64 float4 per pixel
#define RH 3             // output rows per thread
#define HG ((HH + RH - 1) / RH)  // 19 h-groups

__device__ __forceinline__ void fma4(float4& a, const float4& v, const float4& k) {
    a.x = fmaf(v.x, k.x, a.x);
    a.y = fmaf(v.y, k.y, a.y);
    a.z = fmaf(v.z, k.z, a.z);
    a.w = fmaf(v.w, k.w, a.w);
}

__global__ __launch_bounds__(256)
void contour_conv_kernel(const float4* __restrict__ x4,
                         const float4* __restrict__ k4,
                         float4* __restrict__ out4) {
    const int tid = blockIdx.x * blockDim.x + threadIdx.x;
    // total threads = BB * HG * C4 = 32*19*64 = 38912 (grid sized exactly)
    const int c4   = tid & (C4 - 1);
    const int rest = tid >> 6;
    const int hg   = rest % HG;
    const int b    = rest / HG;

    const int h0 = hg * RH;

    // Load the 8 used taps into registers. kern layout [3][3][C]:
    // tap (i,j), channels 4*c4..4*c4+3  ->  k4[(i*3+j)*C4 + c4]
    float4 kt[3][3];
#pragma unroll
    for (int i = 0; i < 3; i++)
#pragma unroll
        for (int j = 0; j < 3; j++)
            kt[i][j] = __ldg(&k4[(i * 3 + j) * C4 + c4]);
    // center tap is masked out by the layer (no self-connection)
    kt[1][1] = make_float4(0.f, 0.f, 0.f, 0.f);

    // float4 index of (b,h,w,c4): ((b*HH + h)*WW + w)*C4 + c4
    const int base_b = (b * HH * WW) * C4 + c4;

    bool rv[RH + 2];
#pragma unroll
    for (int r = 0; r < RH + 2; r++) {
        const int h = h0 - 1 + r;
        rv[r] = (h >= 0) && (h < HH);
    }

    const float4 zero4 = make_float4(0.f, 0.f, 0.f, 0.f);

    // accA -> output col wl-1 (completes this step), accB -> wl, accC -> wl+1
    float4 accA[RH], accB[RH], accC[RH];
    float4 prevc[RH];  // x at column wl-1, center rows (for residual)
#pragma unroll
    for (int r = 0; r < RH; r++) {
        accA[r] = accB[r] = accC[r] = zero4;
        prevc[r] = zero4;
    }

    for (int wl = -1; wl <= WW; wl++) {
        // ---- load fresh column wl (RH+2 rows), zero outside the image ----
        float4 v[RH + 2];
        const bool wvalid = (wl >= 0) && (wl < WW);
#pragma unroll
        for (int r = 0; r < RH + 2; r++) {
            if (wvalid && rv[r]) {
                const int h = h0 - 1 + r;
                v[r] = __ldg(&x4[base_b + (h * WW + wl) * C4]);
            } else {
                v[r] = zero4;
            }
        }

        // ---- scatter column into the three accumulators ----
        // loaded row r (image row h0-1+r) feeds output row ro = r - i, tap row i.
        // accA gets tap col j=2, accB j=1 (skip center i==1), accC j=0.
#pragma unroll
        for (int r = 0; r < RH + 2; r++) {
#pragma unroll
            for (int i = 0; i < 3; i++) {
                const int ro = r - i;
                if (ro >= 0 && ro < RH) {
                    fma4(accA[ro], v[r], kt[i][2]);
                    if (i != 1) fma4(accB[ro], v[r], kt[i][1]);
                    fma4(accC[ro], v[r], kt[i][0]);
                }
            }
        }

        // ---- finalize output column wo = wl - 1 (+ residual) ----
        const int wo = wl - 1;
        if (wo >= 0) {
#pragma unroll
            for (int r = 0; r < RH; r++) {
                const int h = h0 + r;
                if (h < HH) {
                    float4 o = accA[r];
                    o.x += prevc[r].x;
                    o.y += prevc[r].y;
                    o.z += prevc[r].z;
                    o.w += prevc[r].w;
                    out4[base_b + (h * WW + wo) * C4] = o;
                }
            }
        }

        // ---- rotate ----
#pragma unroll
        for (int r = 0; r < RH; r++) {
            accA[r]  = accB[r];
            accB[r]  = accC[r];
            accC[r]  = zero4;
            prevc[r] = v[r + 1];  // center rows at column wl
        }
    }
}

extern "C" void kernel_launch(void* const* d_in, const int* in_sizes, int n_in,
                              void* d_out, int out_size) {
    const float4* x4 = (const float4*)d_in[0];   // x  [32,56,56,256] f32
    const float4* k4 = (const float4*)d_in[1];   // kernel [3,3,256] f32
    float4* o4 = (float4*)d_out;

    const int total_threads = BB * HG * C4;      // 38912
    const int threads = 256;
    const int blocks = total_threads / threads;  // 152 (exact)
    contour_conv_kernel<<<blocks, threads>>>(x4, k4, o4);
}

// round 2
// speedup vs baseline: 1.1685x; 1.1685x over previous
#include <cuda_runtime.h>
#include <cuda_bf16.h>

// ContourIntegrationLayer: depthwise 3x3 conv (center tap zeroed) + residual.
// x: [B,H,W,C]=[32,56,56,256] f32, kernel: [3,3,C] f32, out: same shape.
//
// R1 -> R2: previous version was latency-bound (occ 12.5%, 1 CTA/SM, DRAM 37%).
// Now: one output ROW per thread (RH=1), 448 blocks -> 3 CTAs/SM, ~24 warps/SM.
// Sliding-window along W with 3 rotating column accumulators; pointer-stepped
// addressing; peeled prologue/epilogue for a branchless inner loop.

#define BB 32
#define HH 56
#define WW 56
#define CC 256
#define C4 (CC / 4)      // 64 float4 lanes per pixel

__device__ __forceinline__ void fma4(float4& a, const float4& v, const float4& k) {
    a.x = fmaf(v.x, k.x, a.x);
    a.y = fmaf(v.y, k.y, a.y);
    a.z = fmaf(v.z, k.z, a.z);
    a.w = fmaf(v.w, k.w, a.w);
}
__device__ __forceinline__ void add4(float4& a, const float4& b) {
    a.x += b.x; a.y += b.y; a.z += b.z; a.w += b.w;
}

__global__ __launch_bounds__(256, 3)
void contour_conv_kernel(const float4* __restrict__ x4,
                         const float4* __restrict__ k4,
                         float4* __restrict__ out4) {
    const int tid  = blockIdx.x * blockDim.x + threadIdx.x;
    const int c4   = tid & (C4 - 1);
    const int rest = tid >> 6;
    const int h    = rest % HH;
    const int b    = rest / HH;

    // 8 used taps (center (1,1) is masked out by the layer)
    const float4 k00 = __ldg(&k4[0 * C4 + c4]);
    const float4 k01 = __ldg(&k4[1 * C4 + c4]);
    const float4 k02 = __ldg(&k4[2 * C4 + c4]);
    const float4 k10 = __ldg(&k4[3 * C4 + c4]);
    const float4 k12 = __ldg(&k4[5 * C4 + c4]);
    const float4 k20 = __ldg(&k4[6 * C4 + c4]);
    const float4 k21 = __ldg(&k4[7 * C4 + c4]);
    const float4 k22 = __ldg(&k4[8 * C4 + c4]);

    const bool up = (h > 0);
    const bool dn = (h < HH - 1);
    const float4 z = make_float4(0.f, 0.f, 0.f, 0.f);

    // row pointers at column 0 (float4-indexed); step C4 per column
    const int rowC = (b * HH + h) * WW;
    const float4* pU = x4 + (rowC - WW) * C4 + c4;
    const float4* pC = x4 + rowC * C4 + c4;
    const float4* pD = x4 + (rowC + WW) * C4 + c4;
    float4*       pO = out4 + rowC * C4 + c4;     // output column 0

    // accA -> out col (wl-1), accB -> wl, accC -> wl+1
    float4 accA = z, accB = z, accC = z, prev = z;

    // ---- prologue: column 0 (no store) ----
    {
        float4 v0 = up ? __ldg(pU) : z;
        float4 v1 = __ldg(pC);
        float4 v2 = dn ? __ldg(pD) : z;
        pU += C4; pC += C4; pD += C4;
        fma4(accA, v0, k02); fma4(accA, v1, k12); fma4(accA, v2, k22);
        fma4(accB, v0, k01);                      fma4(accB, v2, k21);
        fma4(accC, v0, k00); fma4(accC, v1, k10); fma4(accC, v2, k20);
        accA = accB; accB = accC; accC = z; prev = v1;
    }

    // ---- main: columns 1..WW-1, store col wl-1 each step ----
#pragma unroll 2
    for (int wl = 1; wl < WW; wl++) {
        float4 v0 = up ? __ldg(pU) : z;
        float4 v1 = __ldg(pC);
        float4 v2 = dn ? __ldg(pD) : z;
        pU += C4; pC += C4; pD += C4;

        fma4(accA, v0, k02); fma4(accA, v1, k12); fma4(accA, v2, k22);
        fma4(accB, v0, k01);                      fma4(accB, v2, k21);
        fma4(accC, v0, k00); fma4(accC, v1, k10); fma4(accC, v2, k20);

        float4 o = accA;
        add4(o, prev);          // residual: x at (h, wl-1)
        *pO = o;
        pO += C4;

        accA = accB; accB = accC; accC = z; prev = v1;
    }

    // ---- epilogue: column WW-1 output (loads at col WW are zero padding) ----
    {
        float4 o = accA;
        add4(o, prev);
        *pO = o;
    }
}

extern "C" void kernel_launch(void* const* d_in, const int* in_sizes, int n_in,
                              void* d_out, int out_size) {
    const float4* x4 = (const float4*)d_in[0];   // x  [32,56,56,256] f32
    const float4* k4 = (const float4*)d_in[1];   // kernel [3,3,256] f32
    float4* o4 = (float4*)d_out;

    const int total_threads = BB * HH * C4;      // 32*56*64 = 114688
    const int threads = 256;
    const int blocks = total_threads / threads;  // 448 (exact)
    contour_conv_kernel<<<blocks, threads>>>(x4, k4, o4);
}

// round 6
// speedup vs baseline: 1.4456x; 1.2371x over previous
#include <cuda_runtime.h>
#include <cuda_bf16.h>

// ContourIntegrationLayer: depthwise 3x3 conv (center tap zeroed) + residual.
// x: [B,H,W,C]=[32,56,56,256] f32, kernel: [3,3,C] f32, out: same shape.
//
// R2 -> R3: loads were consumed in the same iteration they were issued
// (exposed ~240cyc L2 latency per column, issue stuck at 21%). Now the loads
// for column w+1 are issued BEFORE the FMAs of column w consume last
// iteration's values -> load latency hidden behind a full iteration of
// compute. Row neighbors addressed via immediate offsets off one pointer.

#define BB 32
#define HH 56
#define WW 56
#define CC 256
#define C4 (CC / 4)      // 64 float4 lanes per pixel
#define ROWSTEP (WW * C4)  // float4 elements between h rows

__device__ __forceinline__ void fma4(float4& a, const float4& v, const float4& k) {
    a.x = fmaf(v.x, k.x, a.x);
    a.y = fmaf(v.y, k.y, a.y);
    a.z = fmaf(v.z, k.z, a.z);
    a.w = fmaf(v.w, k.w, a.w);
}
__device__ __forceinline__ void add4(float4& a, const float4& b) {
    a.x += b.x; a.y += b.y; a.z += b.z; a.w += b.w;
}

__global__ __launch_bounds__(256, 3)
void contour_conv_kernel(const float4* __restrict__ x4,
                         const float4* __restrict__ k4,
                         float4* __restrict__ out4) {
    const int tid  = blockIdx.x * blockDim.x + threadIdx.x;
    const int c4   = tid & (C4 - 1);
    const int rest = tid >> 6;
    const int h    = rest % HH;
    const int b    = rest / HH;

    // 8 used taps (center (1,1) masked out by the layer)
    const float4 k00 = __ldg(&k4[0 * C4 + c4]);
    const float4 k01 = __ldg(&k4[1 * C4 + c4]);
    const float4 k02 = __ldg(&k4[2 * C4 + c4]);
    const float4 k10 = __ldg(&k4[3 * C4 + c4]);
    const float4 k12 = __ldg(&k4[5 * C4 + c4]);
    const float4 k20 = __ldg(&k4[6 * C4 + c4]);
    const float4 k21 = __ldg(&k4[7 * C4 + c4]);
    const float4 k22 = __ldg(&k4[8 * C4 + c4]);

    const bool up = (h > 0);
    const bool dn = (h < HH - 1);
    const float4 z = make_float4(0.f, 0.f, 0.f, 0.f);

    // center-row pointer at column 0; up/down rows via immediate offsets
    const float4* pC = x4 + ((b * HH + h) * WW) * C4 + c4;
    float4*       pO = out4 + ((b * HH + h) * WW) * C4 + c4;

    // acc0 -> out(w-1), acc1 -> out(w), acc2 -> out(w+1)
    float4 acc0 = z, acc1 = z, acc2 = z, prev = z;
    float4 vc0, vc1, vc2;   // column currently being integrated
    float4 vn0, vn1, vn2;   // next column (in flight)

    // ---- peel w = 0: load col 0 AND col 1, integrate col 0, no store ----
    vc0 = up ? __ldg(pC - ROWSTEP) : z;
    vc1 = __ldg(pC);
    vc2 = dn ? __ldg(pC + ROWSTEP) : z;
    pC += C4;
    vn0 = up ? __ldg(pC - ROWSTEP) : z;
    vn1 = __ldg(pC);
    vn2 = dn ? __ldg(pC + ROWSTEP) : z;
    pC += C4;

    fma4(acc0, vc0, k02); fma4(acc0, vc1, k12); fma4(acc0, vc2, k22);
    fma4(acc1, vc0, k01);                       fma4(acc1, vc2, k21);
    fma4(acc2, vc0, k00); fma4(acc2, vc1, k10); fma4(acc2, vc2, k20);
    prev = vc1;
    acc0 = acc1; acc1 = acc2; acc2 = z;
    vc0 = vn0; vc1 = vn1; vc2 = vn2;

    // ---- main: w = 1 .. WW-2 ----
    // top: issue loads for column w+1; body: consume column w (already loaded)
#pragma unroll 2
    for (int w = 1; w < WW - 1; w++) {
        vn0 = up ? __ldg(pC - ROWSTEP) : z;
        vn1 = __ldg(pC);
        vn2 = dn ? __ldg(pC + ROWSTEP) : z;
        pC += C4;

        fma4(acc0, vc0, k02); fma4(acc0, vc1, k12); fma4(acc0, vc2, k22);
        fma4(acc1, vc0, k01);                       fma4(acc1, vc2, k21);
        fma4(acc2, vc0, k00); fma4(acc2, vc1, k10); fma4(acc2, vc2, k20);

        float4 o = acc0;
        add4(o, prev);                 // residual: x(h, w-1)
        *pO = o;
        pO += C4;

        prev = vc1;
        acc0 = acc1; acc1 = acc2; acc2 = z;
        vc0 = vn0; vc1 = vn1; vc2 = vn2;
    }

    // ---- peel w = WW-1: integrate last column (col WW would be zero-pad) ----
    fma4(acc0, vc0, k02); fma4(acc0, vc1, k12); fma4(acc0, vc2, k22);
    fma4(acc1, vc0, k01);                       fma4(acc1, vc2, k21);

    {
        float4 o = acc0;
        add4(o, prev);                 // out(WW-2)
        *pO = o;
        pO += C4;
    }

    // ---- epilogue: out(WW-1) = acc1 + residual x(h, WW-1) ----
    {
        float4 o = acc1;
        add4(o, vc1);
        *pO = o;
    }
}

extern "C" void kernel_launch(void* const* d_in, const int* in_sizes, int n_in,
                              void* d_out, int out_size) {
    const float4* x4 = (const float4*)d_in[0];   // x  [32,56,56,256] f32
    const float4* k4 = (const float4*)d_in[1];   // kernel [3,3,256] f32
    float4* o4 = (float4*)d_out;

    const int total_threads = BB * HH * C4;      // 32*56*64 = 114688
    const int threads = 256;
    const int blocks = total_threads / threads;  // 448 (exact)
    contour_conv_kernel<<<blocks, threads>>>(x4, k4, o4);
}